// round 12
// baseline (speedup 1.0000x reference)
#include <cuda_runtime.h>
#include <cuda_bf16.h>

// Problem shape (fixed by reference)
#define BATCH 4096
#define SLOTS 26
#define MAX_NNZ 10
#define EMB 64
#define NUM_SLOTS (BATCH * SLOTS)          // 106496 (b,s) pairs
#define GROUPS (NUM_SLOTS / 2)             // 53248 -> each half-warp handles 2 slots
#define LANES_PER_SLOT 16

// 2x thread coarsening: each 16-lane group processes slots {2g, 2g+1}.
// Their 20 keys/masks are contiguous; both key batches load up-front, so slot
// B's gathers issue immediately after slot A's (no second key-latency bubble),
// and each thread carries up to 20 independent gather LDG.128s.
// Total threads = GROUPS*16 = 851,968 = 3328 blocks * 256 exactly -> no tail.
__global__ __launch_bounds__(256, 5) void emb_combine_kernel(
    const int* __restrict__ keys,    // [B, S, N]
    const int* __restrict__ mask,    // [B, S, N]  (bool as int32; nonzero = valid)
    const float* __restrict__ table, // [VOCAB, EMB]
    float* __restrict__ out)         // [B, S, EMB]
{
    const int gtid   = blockIdx.x * blockDim.x + threadIdx.x;
    const int group  = gtid >> 4;          // 16 threads per 2-slot group
    const int lane16 = gtid & 15;
    const unsigned lane = threadIdx.x & 31;
    const int halfbase  = lane & 16;       // 0 or 16

    const int slotA = group * 2;
    const int baseA = slotA * MAX_NNZ;     // 20*group
    const int baseB = baseA + MAX_NNZ;

    // Cooperative key/mask load for BOTH slots up-front (4 loads in lanes < 10).
    int mkA = -1, mkB = -1;
    if (lane16 < MAX_NNZ) {
        int mA = __ldg(&mask[baseA + lane16]);
        int kA = __ldg(&keys[baseA + lane16]);
        int mB = __ldg(&mask[baseB + lane16]);
        int kB = __ldg(&keys[baseB + lane16]);
        mkA = mA ? kA : -1;
        mkB = mB ? kB : -1;
    }

    unsigned balA = __ballot_sync(0xFFFFFFFFu, mkA >= 0);
    unsigned balB = __ballot_sync(0xFFFFFFFFu, mkB >= 0);
    int cntA = __popc((balA >> halfbase) & 0xFFFFu);
    int cntB = __popc((balB >> halfbase) & 0xFFFFu);

    float4 accA = make_float4(0.f, 0.f, 0.f, 0.f);
    float4 accB = make_float4(0.f, 0.f, 0.f, 0.f);

#pragma unroll
    for (int j = 0; j < MAX_NNZ; j++) {
        int kA = __shfl_sync(0xFFFFFFFFu, mkA, halfbase + j);
        int kB = __shfl_sync(0xFFFFFFFFu, mkB, halfbase + j);
        if (kA >= 0) {
            float4 v = __ldg(reinterpret_cast<const float4*>(table + (size_t)kA * EMB) + lane16);
            accA.x += v.x; accA.y += v.y; accA.z += v.z; accA.w += v.w;
        }
        if (kB >= 0) {
            float4 v = __ldg(reinterpret_cast<const float4*>(table + (size_t)kB * EMB) + lane16);
            accB.x += v.x; accB.y += v.y; accB.z += v.z; accB.w += v.w;
        }
    }

    float invA = 1.0f / (float)(cntA > 0 ? cntA : 1);
    float invB = 1.0f / (float)(cntB > 0 ? cntB : 1);
    accA.x *= invA; accA.y *= invA; accA.z *= invA; accA.w *= invA;
    accB.x *= invB; accB.y *= invB; accB.z *= invB; accB.w *= invB;

    reinterpret_cast<float4*>(out + (size_t)slotA * EMB)[lane16]       = accA;
    reinterpret_cast<float4*>(out + (size_t)(slotA + 1) * EMB)[lane16] = accB;
}

extern "C" void kernel_launch(void* const* d_in, const int* in_sizes, int n_in,
                              void* d_out, int out_size) {
    const int*   keys  = (const int*)d_in[0];
    const int*   mask  = (const int*)d_in[1];
    const float* table = (const float*)d_in[2];
    float*       out   = (float*)d_out;

    const int total_threads = GROUPS * LANES_PER_SLOT;  // 851,968
    const int block = 256;
    const int grid = (total_threads + block - 1) / block;  // 3328, exact
    emb_combine_kernel<<<grid, block>>>(keys, mask, table, out);
}

// round 13
// speedup vs baseline: 1.0091x; 1.0091x over previous
#include <cuda_runtime.h>
#include <cuda_bf16.h>

// Problem shape (fixed by reference)
#define BATCH 4096
#define SLOTS 26
#define MAX_NNZ 10
#define EMB 64
#define NUM_SLOTS (BATCH * SLOTS)          // 106496 (b,s) pairs
#define SLOTS_PER_BLOCK 16                 // 256 threads / 16 lanes per slot
#define KEYS_PER_BLOCK (SLOTS_PER_BLOCK * MAX_NNZ)   // 160

// Block-level key staging: one coalesced prologue folds keys+mask into smem,
// then the gather loop reads them via LDS broadcast. Removes the per-half-warp
// key-latency bubble, the ballot, and the 10-SHFL dependency chain from every
// warp's critical path, while keeping live registers <=32 (8 blocks/SM).
// Grid = NUM_SLOTS/16 = 6656 blocks exactly -> no tail anywhere.
__global__ __launch_bounds__(256, 8) void emb_combine_kernel(
    const int* __restrict__ keys,    // [B, S, N]
    const int* __restrict__ mask,    // [B, S, N]  (bool as int32; nonzero = valid)
    const float* __restrict__ table, // [VOCAB, EMB]
    float* __restrict__ out)         // [B, S, EMB]
{
    __shared__ int s_mk[KEYS_PER_BLOCK];   // folded key: valid ? key : -1

    const int tid = threadIdx.x;
    const int block_key_base = blockIdx.x * KEYS_PER_BLOCK;

    // Prologue: 160 contiguous key+mask loads, fully coalesced, once per block.
    if (tid < KEYS_PER_BLOCK) {
        int k = __ldg(&keys[block_key_base + tid]);
        int m = __ldg(&mask[block_key_base + tid]);
        s_mk[tid] = m ? k : -1;
    }
    __syncthreads();

    const int slot_local = tid >> 4;       // 0..15
    const int lane16     = tid & 15;       // which float4 of the 64-float row
    const int slot       = blockIdx.x * SLOTS_PER_BLOCK + slot_local;
    const int mk_base    = slot_local * MAX_NNZ;

    float4 acc = make_float4(0.f, 0.f, 0.f, 0.f);
    int cnt = 0;

#pragma unroll
    for (int j = 0; j < MAX_NNZ; j++) {
        int kj = s_mk[mk_base + j];        // LDS broadcast across the 16 lanes
        if (kj >= 0) {
            float4 v = __ldg(reinterpret_cast<const float4*>(table + (size_t)kj * EMB) + lane16);
            acc.x += v.x; acc.y += v.y; acc.z += v.z; acc.w += v.w;
            cnt++;
        }
    }

    // mean combiner: divide by max(count, 1)
    float inv = 1.0f / (float)(cnt > 0 ? cnt : 1);
    acc.x *= inv; acc.y *= inv; acc.z *= inv; acc.w *= inv;

    reinterpret_cast<float4*>(out + (size_t)slot * EMB)[lane16] = acc;
}

extern "C" void kernel_launch(void* const* d_in, const int* in_sizes, int n_in,
                              void* d_out, int out_size) {
    const int*   keys  = (const int*)d_in[0];
    const int*   mask  = (const int*)d_in[1];
    const float* table = (const float*)d_in[2];
    float*       out   = (float*)d_out;

    const int grid = NUM_SLOTS / SLOTS_PER_BLOCK;   // 6656, exact
    emb_combine_kernel<<<grid, 256>>>(keys, mask, table, out);
}